// round 15
// baseline (speedup 1.0000x reference)
#include <cuda_runtime.h>
#include <cuda_fp16.h>
#include <cstdint>

#define Bn 32
#define Gn 512
#define Dn 128
#define Hn 4
#define NORMF 0.17677669529663687f   // 1/sqrt(32)

// Scratch (device globals — no allocation allowed)
__device__ uint32_t g_Ah2 [Bn * Gn * 16];   // fc1 i-side partial, half2, perm-k
__device__ uint32_t g_Bvh2[Bn * Gn * 16];   // fc1 j-side partial + b1, half2, perm-k

// -------------------------------------------------------------------------
// prep (fused): grid (4, Bn), 256 threads.
// Phase A: (hh,k4,dq) units — float4 Wq loads shared by all 4 maps.
// Phase B: M-fold. Phase C: per-g compat + fc1 fold (2 threads/g).
// -------------------------------------------------------------------------
__global__ void __launch_bounds__(256) prep(const float* __restrict__ h,
                                            const int* __restrict__ pp,
                                            const int* __restrict__ pd,
                                            const int* __restrict__ rec,
                                            const float* __restrict__ Wq1,
                                            const float* __restrict__ Wk1,
                                            const float* __restrict__ Wq2,
                                            const float* __restrict__ Wk2,
                                            const float* __restrict__ FC1W,
                                            const float* __restrict__ FC1B) {
    int b   = blockIdx.y;
    int t   = threadIdx.x;
    int gl  = t & 127;
    int half = t >> 7;
    int g   = blockIdx.x * 128 + gl;

    __shared__ float shp[Dn], shd[Dn];
    __shared__ float sQp[4][4][Hn][32]; // [dq][map][hh][k]  (8KB)
    __shared__ float sQ[4][Hn][32];     // [map][hh][k]
    __shared__ float sM[4][Hn][Dn];     // [map][hh][d]      (8KB)
    __shared__ float sW1[16][32];
    __shared__ float sB1[32];
    __shared__ float sX[128][8];
    __shared__ float sY[128][8];

    int ip = pp[b], id = pd[b];
    if (t < Dn)      shp[t]       = h[(b * Gn + ip) * Dn + t];
    else             shd[t - Dn]  = h[(b * Gn + id) * Dn + (t - Dn)];
    for (int idx = t; idx < 512; idx += 256) ((float*)sW1)[idx] = __ldg(&FC1W[idx]);
    if (t < 32) sB1[t] = __ldg(&FC1B[t]);
    __syncthreads();

    // ---- phase A: Q partials; weight loads shared across all 4 maps ----
    if (t < 128) {
        int dq = t & 3, k4 = (t >> 2) & 7, hh = t >> 5;
        float acc[4][4];
        #pragma unroll
        for (int m = 0; m < 4; m++)
            #pragma unroll
            for (int kk = 0; kk < 4; kk++) acc[m][kk] = 0.f;
        #pragma unroll 4
        for (int dd = 0; dd < 32; dd++) {
            int d = dq * 32 + dd;
            float4 w1 = __ldg((const float4*)&Wq1[(hh * Dn + d) * 32 + k4 * 4]);
            float4 w2 = __ldg((const float4*)&Wq2[(hh * Dn + d) * 32 + k4 * 4]);
            float xp = shp[d], xd = shd[d];
            acc[0][0] = fmaf(xp, w1.x, acc[0][0]); acc[0][1] = fmaf(xp, w1.y, acc[0][1]);
            acc[0][2] = fmaf(xp, w1.z, acc[0][2]); acc[0][3] = fmaf(xp, w1.w, acc[0][3]);
            acc[1][0] = fmaf(xp, w2.x, acc[1][0]); acc[1][1] = fmaf(xp, w2.y, acc[1][1]);
            acc[1][2] = fmaf(xp, w2.z, acc[1][2]); acc[1][3] = fmaf(xp, w2.w, acc[1][3]);
            acc[2][0] = fmaf(xd, w1.x, acc[2][0]); acc[2][1] = fmaf(xd, w1.y, acc[2][1]);
            acc[2][2] = fmaf(xd, w1.z, acc[2][2]); acc[2][3] = fmaf(xd, w1.w, acc[2][3]);
            acc[3][0] = fmaf(xd, w2.x, acc[3][0]); acc[3][1] = fmaf(xd, w2.y, acc[3][1]);
            acc[3][2] = fmaf(xd, w2.z, acc[3][2]); acc[3][3] = fmaf(xd, w2.w, acc[3][3]);
        }
        #pragma unroll
        for (int m = 0; m < 4; m++)
            #pragma unroll
            for (int kk = 0; kk < 4; kk++)
                sQp[dq][m][hh][k4 * 4 + kk] = acc[m][kk];
    }
    __syncthreads();
    #pragma unroll
    for (int e0 = 0; e0 < 2; e0++) {
        int e = t + e0 * 256;
        int m = e >> 7, hk = e & 127, hh = hk >> 5, k = hk & 31;
        sQ[m][hh][k] = (sQp[0][m][hh][k] + sQp[1][m][hh][k])
                     + (sQp[2][m][hh][k] + sQp[3][m][hh][k]);
    }
    __syncthreads();

    // ---- phase B: M[map][hh][d] (2048 entries, 8/thread), 4 accumulators ----
    #pragma unroll
    for (int e0 = 0; e0 < 8; e0++) {
        int e = t + e0 * 256;
        int m = e >> 9, rest = e & 511, hh = rest >> 7, d = rest & 127;
        const float* wk = (m & 1) ? Wk2 : Wk1;
        const float4* wr = (const float4*)&wk[(hh * Dn + d) * 32];
        float a0 = 0.f, a1 = 0.f, a2 = 0.f, a3 = 0.f;
        #pragma unroll
        for (int i4 = 0; i4 < 8; i4++) {
            float4 a = __ldg(wr + i4);
            int k0 = i4 * 4;
            a0 = fmaf(sQ[m][hh][k0 + 0], a.x, a0);
            a1 = fmaf(sQ[m][hh][k0 + 1], a.y, a1);
            a2 = fmaf(sQ[m][hh][k0 + 2], a.z, a2);
            a3 = fmaf(sQ[m][hh][k0 + 3], a.w, a3);
        }
        sM[m][hh][d] = ((a0 + a1) + (a2 + a3)) * NORMF;
    }
    __syncthreads();

    // ---- phase C: per-g compat + fc1 fold (2 threads per g) ----
    int nb = rec[b * Gn + g];
    const float4* hrow = (const float4*)(h + (b * Gn + g) * Dn)  + half * 16;
    const float4* nrow = (const float4*)(h + (b * Gn + nb) * Dn) + half * 16;

    float u[8], v[8];
    #pragma unroll
    for (int l = 0; l < 8; l++) { u[l] = 0.f; v[l] = 0.f; }

    #pragma unroll 4
    for (int d4 = 0; d4 < 16; d4++) {
        float4 xv = __ldg(hrow + d4);
        float4 yv = __ldg(nrow + d4);
        float xs[4] = {xv.x, xv.y, xv.z, xv.w};
        float ys[4] = {yv.x, yv.y, yv.z, yv.w};
        #pragma unroll
        for (int r = 0; r < 4; r++) {
            int d = half * 64 + d4 * 4 + r;
            #pragma unroll
            for (int hh = 0; hh < Hn; hh++) {
                u[hh]     = fmaf(xs[r], sM[0][hh][d], u[hh]);
                u[4 + hh] = fmaf(ys[r], sM[1][hh][d], u[4 + hh]);
                v[hh]     = fmaf(xs[r], sM[2][hh][d], v[hh]);
                v[4 + hh] = fmaf(ys[r], sM[3][hh][d], v[4 + hh]);
            }
        }
    }
    if (half == 1) {
        #pragma unroll
        for (int l = 0; l < 8; l++) sX[gl][l] = u[l];
    } else {
        #pragma unroll
        for (int l = 0; l < 8; l++) sY[gl][l] = v[l];
    }
    __syncthreads();

    float z[8];
    if (half == 0) {
        #pragma unroll
        for (int l = 0; l < 8; l++) z[l] = u[l] + sX[gl][l];   // full u
    } else {
        #pragma unroll
        for (int l = 0; l < 8; l++) z[l] = sY[gl][l] + v[l];   // full v
    }

    float res[32];
    const float* Wslice = half ? &sW1[8][0] : &sW1[0][0];
    #pragma unroll
    for (int k = 0; k < 32; k++) {
        float a = half ? sB1[k] : 0.f;
        #pragma unroll
        for (int l = 0; l < 8; l++)
            a = fmaf(z[l], Wslice[l * 32 + k], a);
        res[k] = a;
    }

    uint32_t pk[16];
    #pragma unroll
    for (int m = 0; m < 16; m++) {
        int c = m >> 3, rem = m & 7, qq = rem >> 1, s = rem & 1;
        int k0 = 16 * c + 2 * qq + 8 * s;
        __half2 hp = __floats2half2_rn(res[k0], res[k0 + 1]);
        pk[m] = *(uint32_t*)&hp;
    }
    uint4* dst = half ? (uint4*)&g_Bvh2[(b * Gn + g) * 16]
                      : (uint4*)&g_Ah2 [(b * Gn + g) * 16];
    #pragma unroll
    for (int c4 = 0; c4 < 4; c4++)
        dst[c4] = make_uint4(pk[4*c4], pk[4*c4+1], pk[4*c4+2], pk[4*c4+3]);
}

// -------------------------------------------------------------------------
// mlp_mma: fc2 via mma m16n8k16 fp16 (f32 acc, bias pre-init), fc3 via MMA
// pair. Two i's per warp share pipelined Bv loads. 3 CTAs/SM.
// -------------------------------------------------------------------------
#define BV_STRIDE 24   // uint32 per smem row (96B)

__global__ void __launch_bounds__(256, 3) mlp_mma(const float* __restrict__ W2,
                                                  const float* __restrict__ B2,
                                                  const float* __restrict__ W3,
                                                  const float* __restrict__ B3,
                                                  float* __restrict__ out) {
    extern __shared__ uint32_t sBv2[];   // [512][BV_STRIDE]
    const int t = threadIdx.x;
    const int w = t >> 5;
    const int lane = t & 31;
    const int q = lane & 3;          // threadID_in_group
    const int r = lane >> 2;         // groupID
    const int b = blockIdx.y;
    const int i0 = blockIdx.x * 16 + w * 2;   // this warp's two i's

    // ---- stage Bvh[b] into smem ----
    {
        const uint4* src = (const uint4*)&g_Bvh2[b * Gn * 16];
        for (int idx = t; idx < Gn * 4; idx += 256) {
            int j = idx >> 2, c4 = idx & 3;
            uint4 v = __ldg(src + idx);
            *(uint4*)&sBv2[j * BV_STRIDE + c4 * 4] = v;
        }
    }

    // ---- loop-invariant per-thread data ----
    uint2 Ah[2][2];   // [i][chunk]
    #pragma unroll
    for (int p = 0; p < 2; p++) {
        const uint32_t* ar = &g_Ah2[(b * Gn + i0 + p) * 16];
        Ah[p][0] = *(const uint2*)&ar[2 * q];
        Ah[p][1] = *(const uint2*)&ar[8 + 2 * q];
    }
    uint32_t wb[4][2][2];
    #pragma unroll
    for (int nbk = 0; nbk < 4; nbk++)
        #pragma unroll
        for (int c = 0; c < 2; c++) {
            int n = 8 * nbk + r;
            __half2 w0 = __floats2half2_rn(__ldg(&W2[(16*c + 2*q)     * 32 + n]),
                                           __ldg(&W2[(16*c + 2*q + 1) * 32 + n]));
            __half2 w1 = __floats2half2_rn(__ldg(&W2[(16*c + 2*q + 8) * 32 + n]),
                                           __ldg(&W2[(16*c + 2*q + 9) * 32 + n]));
            wb[nbk][c][0] = *(uint32_t*)&w0;
            wb[nbk][c][1] = *(uint32_t*)&w1;
        }
    uint32_t wb3[2][2];
    #pragma unroll
    for (int c = 0; c < 2; c++) {
        __half2 w0 = __floats2half2_rn(__ldg(&W3[16*c + 2*q]),
                                       __ldg(&W3[16*c + 2*q + 1]));
        __half2 w1 = __floats2half2_rn(__ldg(&W3[16*c + 2*q + 8]),
                                       __ldg(&W3[16*c + 2*q + 9]));
        wb3[c][0] = *(uint32_t*)&w0;
        wb3[c][1] = *(uint32_t*)&w1;
    }
    float b2v[4][2];
    #pragma unroll
    for (int nbk = 0; nbk < 4; nbk++) {
        b2v[nbk][0] = __ldg(&B2[8 * nbk + 2 * q]);
        b2v[nbk][1] = __ldg(&B2[8 * nbk + 2 * q + 1]);
    }
    const float b3 = __ldg(&B3[0]);
    const __half2 hz = __float2half2_rn(0.f);
    __syncthreads();

    float* outrow0 = out + ((size_t)(b * Gn + i0))     * Gn;
    float* outrow1 = out + ((size_t)(b * Gn + i0 + 1)) * Gn;
    const uint32_t* bvlo = sBv2 + r * BV_STRIDE + 2 * q;
    const uint32_t* bvhi = sBv2 + (r + 8) * BV_STRIDE + 2 * q;

    // prologue: load fragments for jt = 0
    uint2 rl[2], rh[2];
    rl[0] = *(const uint2*)(bvlo + 0); rl[1] = *(const uint2*)(bvlo + 8);
    rh[0] = *(const uint2*)(bvhi + 0); rh[1] = *(const uint2*)(bvhi + 8);

    for (int jt = 0; jt < 32; jt++) {
        const int j0 = jt * 16;
        // prefetch next tile's fragments (clamped; unused on last iter)
        const int jn = (jt < 31) ? (j0 + 16) : 0;
        const uint32_t* npl = bvlo + jn * BV_STRIDE;
        const uint32_t* nph = bvhi + jn * BV_STRIDE;
        uint2 nl0 = *(const uint2*)(npl + 0);
        uint2 nl1 = *(const uint2*)(npl + 8);
        uint2 nh0 = *(const uint2*)(nph + 0);
        uint2 nh1 = *(const uint2*)(nph + 8);

        float acc[2][4][4];
        #pragma unroll
        for (int p = 0; p < 2; p++)
            #pragma unroll
            for (int nbk = 0; nbk < 4; nbk++) {
                acc[p][nbk][0] = b2v[nbk][0]; acc[p][nbk][1] = b2v[nbk][1];
                acc[p][nbk][2] = b2v[nbk][0]; acc[p][nbk][3] = b2v[nbk][1];
            }

        #pragma unroll
        for (int c = 0; c < 2; c++) {
            uint32_t a[2][4];
            #pragma unroll
            for (int p = 0; p < 2; p++) {
                __half2 av0 = *(__half2*)&Ah[p][c].x;
                __half2 av1 = *(__half2*)&Ah[p][c].y;
                __half2 f0 = __hmax2(__hadd2(av0, *(__half2*)&rl[c].x), hz);
                __half2 f1 = __hmax2(__hadd2(av0, *(__half2*)&rh[c].x), hz);
                __half2 f2 = __hmax2(__hadd2(av1, *(__half2*)&rl[c].y), hz);
                __half2 f3 = __hmax2(__hadd2(av1, *(__half2*)&rh[c].y), hz);
                a[p][0] = *(uint32_t*)&f0; a[p][1] = *(uint32_t*)&f1;
                a[p][2] = *(uint32_t*)&f2; a[p][3] = *(uint32_t*)&f3;
            }
            #pragma unroll
            for (int nbk = 0; nbk < 4; nbk++)
                #pragma unroll
                for (int p = 0; p < 2; p++) {
                    asm volatile(
                        "mma.sync.aligned.m16n8k16.row.col.f32.f16.f16.f32 "
                        "{%0,%1,%2,%3}, {%4,%5,%6,%7}, {%8,%9}, {%0,%1,%2,%3};"
                        : "+f"(acc[p][nbk][0]), "+f"(acc[p][nbk][1]),
                          "+f"(acc[p][nbk][2]), "+f"(acc[p][nbk][3])
                        : "r"(a[p][0]), "r"(a[p][1]), "r"(a[p][2]), "r"(a[p][3]),
                          "r"(wb[nbk][c][0]), "r"(wb[nbk][c][1]));
                }
        }

        // rotate prefetched fragments in
        rl[0] = nl0; rl[1] = nl1; rh[0] = nh0; rh[1] = nh1;

        // ---- epilogue: relu-pack acc as A-fragments, fc3 via 2 HMMA/i ----
        float o[2][2];
        #pragma unroll
        for (int p = 0; p < 2; p++) {
            float o0 = b3, o1 = 0.f, o2 = b3, o3 = 0.f;
            #pragma unroll
            for (int c = 0; c < 2; c++) {
                __half2 g0 = __hmax2(__floats2half2_rn(acc[p][2*c][0],   acc[p][2*c][1]),   hz);
                __half2 g1 = __hmax2(__floats2half2_rn(acc[p][2*c][2],   acc[p][2*c][3]),   hz);
                __half2 g2 = __hmax2(__floats2half2_rn(acc[p][2*c+1][0], acc[p][2*c+1][1]), hz);
                __half2 g3 = __hmax2(__floats2half2_rn(acc[p][2*c+1][2], acc[p][2*c+1][3]), hz);
                uint32_t a0 = *(uint32_t*)&g0, a1 = *(uint32_t*)&g1;
                uint32_t a2 = *(uint32_t*)&g2, a3 = *(uint32_t*)&g3;
                asm volatile(
                    "mma.sync.aligned.m16n8k16.row.col.f32.f16.f16.f32 "
                    "{%0,%1,%2,%3}, {%4,%5,%6,%7}, {%8,%9}, {%0,%1,%2,%3};"
                    : "+f"(o0), "+f"(o1), "+f"(o2), "+f"(o3)
                    : "r"(a0), "r"(a1), "r"(a2), "r"(a3),
                      "r"(wb3[c][0]), "r"(wb3[c][1]));
            }
            o[p][0] = o0; o[p][1] = o2;
        }
        if (q == 0) {
            outrow0[j0 + r]     = o[0][0];
            outrow0[j0 + 8 + r] = o[0][1];
            outrow1[j0 + r]     = o[1][0];
            outrow1[j0 + 8 + r] = o[1][1];
        }
    }
}

// -------------------------------------------------------------------------
extern "C" void kernel_launch(void* const* d_in, const int* in_sizes, int n_in,
                              void* d_out, int out_size) {
    const float* h    = (const float*)d_in[0];
    const int*   pp   = (const int*)  d_in[1];
    const int*   pd   = (const int*)  d_in[2];
    const int*   rec  = (const int*)  d_in[3];
    const float* Wq1  = (const float*)d_in[4];
    const float* Wk1  = (const float*)d_in[5];
    const float* Wq2  = (const float*)d_in[6];
    const float* Wk2  = (const float*)d_in[7];
    const float* FC1W = (const float*)d_in[8];
    const float* FC1B = (const float*)d_in[9];
    const float* W2   = (const float*)d_in[10];
    const float* B2   = (const float*)d_in[11];
    const float* W3   = (const float*)d_in[12];
    const float* B3   = (const float*)d_in[13];

    const int smem_bytes = Gn * BV_STRIDE * sizeof(uint32_t);   // 49152
    static int smem_set = 0;
    if (!smem_set) {
        cudaFuncSetAttribute(mlp_mma, cudaFuncAttributeMaxDynamicSharedMemorySize, smem_bytes);
        smem_set = 1;
    }

    prep<<<dim3(4, Bn), 256>>>(h, pp, pd, rec, Wq1, Wk1, Wq2, Wk2, FC1W, FC1B);
    mlp_mma<<<dim3(Gn / 16, Bn), 256, smem_bytes>>>(W2, B2, W3, B3, (float*)d_out);
}

// round 16
// speedup vs baseline: 1.1293x; 1.1293x over previous
#include <cuda_runtime.h>
#include <cuda_fp16.h>
#include <cstdint>

#define Bn 32
#define Gn 512
#define Dn 128
#define Hn 4
#define NORMF 0.17677669529663687f   // 1/sqrt(32)

// Scratch (device globals — no allocation allowed)
__device__ uint32_t g_Ah2 [Bn * Gn * 16];   // fc1 i-side partial, half2, perm-k
__device__ uint32_t g_Bvh2[Bn * Gn * 16];   // fc1 j-side partial + b1, half2, perm-k

// -------------------------------------------------------------------------
// prep (fused): grid (4, Bn), 256 threads.
// Phase A: (hh,k4,dq) units — float4 Wq loads shared by all 4 maps.
// Phase B: M-fold. Phase C: per-g compat + fc1 fold (2 threads/g).
// -------------------------------------------------------------------------
__global__ void __launch_bounds__(256) prep(const float* __restrict__ h,
                                            const int* __restrict__ pp,
                                            const int* __restrict__ pd,
                                            const int* __restrict__ rec,
                                            const float* __restrict__ Wq1,
                                            const float* __restrict__ Wk1,
                                            const float* __restrict__ Wq2,
                                            const float* __restrict__ Wk2,
                                            const float* __restrict__ FC1W,
                                            const float* __restrict__ FC1B) {
    int b   = blockIdx.y;
    int t   = threadIdx.x;
    int gl  = t & 127;
    int half = t >> 7;
    int g   = blockIdx.x * 128 + gl;

    __shared__ float shp[Dn], shd[Dn];
    __shared__ float sQp[4][4][Hn][32]; // [dq][map][hh][k]  (8KB)
    __shared__ float sQ[4][Hn][32];     // [map][hh][k]
    __shared__ float sM[4][Hn][Dn];     // [map][hh][d]      (8KB)
    __shared__ float sW1[16][32];
    __shared__ float sB1[32];
    __shared__ float sX[128][8];
    __shared__ float sY[128][8];

    int ip = pp[b], id = pd[b];
    if (t < Dn)      shp[t]       = h[(b * Gn + ip) * Dn + t];
    else             shd[t - Dn]  = h[(b * Gn + id) * Dn + (t - Dn)];
    for (int idx = t; idx < 512; idx += 256) ((float*)sW1)[idx] = __ldg(&FC1W[idx]);
    if (t < 32) sB1[t] = __ldg(&FC1B[t]);
    __syncthreads();

    // ---- phase A: Q partials; weight loads shared across all 4 maps ----
    if (t < 128) {
        int dq = t & 3, k4 = (t >> 2) & 7, hh = t >> 5;
        float acc[4][4];
        #pragma unroll
        for (int m = 0; m < 4; m++)
            #pragma unroll
            for (int kk = 0; kk < 4; kk++) acc[m][kk] = 0.f;
        #pragma unroll 4
        for (int dd = 0; dd < 32; dd++) {
            int d = dq * 32 + dd;
            float4 w1 = __ldg((const float4*)&Wq1[(hh * Dn + d) * 32 + k4 * 4]);
            float4 w2 = __ldg((const float4*)&Wq2[(hh * Dn + d) * 32 + k4 * 4]);
            float xp = shp[d], xd = shd[d];
            acc[0][0] = fmaf(xp, w1.x, acc[0][0]); acc[0][1] = fmaf(xp, w1.y, acc[0][1]);
            acc[0][2] = fmaf(xp, w1.z, acc[0][2]); acc[0][3] = fmaf(xp, w1.w, acc[0][3]);
            acc[1][0] = fmaf(xp, w2.x, acc[1][0]); acc[1][1] = fmaf(xp, w2.y, acc[1][1]);
            acc[1][2] = fmaf(xp, w2.z, acc[1][2]); acc[1][3] = fmaf(xp, w2.w, acc[1][3]);
            acc[2][0] = fmaf(xd, w1.x, acc[2][0]); acc[2][1] = fmaf(xd, w1.y, acc[2][1]);
            acc[2][2] = fmaf(xd, w1.z, acc[2][2]); acc[2][3] = fmaf(xd, w1.w, acc[2][3]);
            acc[3][0] = fmaf(xd, w2.x, acc[3][0]); acc[3][1] = fmaf(xd, w2.y, acc[3][1]);
            acc[3][2] = fmaf(xd, w2.z, acc[3][2]); acc[3][3] = fmaf(xd, w2.w, acc[3][3]);
        }
        #pragma unroll
        for (int m = 0; m < 4; m++)
            #pragma unroll
            for (int kk = 0; kk < 4; kk++)
                sQp[dq][m][hh][k4 * 4 + kk] = acc[m][kk];
    }
    __syncthreads();
    #pragma unroll
    for (int e0 = 0; e0 < 2; e0++) {
        int e = t + e0 * 256;
        int m = e >> 7, hk = e & 127, hh = hk >> 5, k = hk & 31;
        sQ[m][hh][k] = (sQp[0][m][hh][k] + sQp[1][m][hh][k])
                     + (sQp[2][m][hh][k] + sQp[3][m][hh][k]);
    }
    __syncthreads();

    // ---- phase B: M[map][hh][d] (2048 entries, 8/thread), 4 accumulators ----
    #pragma unroll
    for (int e0 = 0; e0 < 8; e0++) {
        int e = t + e0 * 256;
        int m = e >> 9, rest = e & 511, hh = rest >> 7, d = rest & 127;
        const float* wk = (m & 1) ? Wk2 : Wk1;
        const float4* wr = (const float4*)&wk[(hh * Dn + d) * 32];
        float a0 = 0.f, a1 = 0.f, a2 = 0.f, a3 = 0.f;
        #pragma unroll
        for (int i4 = 0; i4 < 8; i4++) {
            float4 a = __ldg(wr + i4);
            int k0 = i4 * 4;
            a0 = fmaf(sQ[m][hh][k0 + 0], a.x, a0);
            a1 = fmaf(sQ[m][hh][k0 + 1], a.y, a1);
            a2 = fmaf(sQ[m][hh][k0 + 2], a.z, a2);
            a3 = fmaf(sQ[m][hh][k0 + 3], a.w, a3);
        }
        sM[m][hh][d] = ((a0 + a1) + (a2 + a3)) * NORMF;
    }
    __syncthreads();

    // ---- phase C: per-g compat + fc1 fold (2 threads per g) ----
    int nb = rec[b * Gn + g];
    const float4* hrow = (const float4*)(h + (b * Gn + g) * Dn)  + half * 16;
    const float4* nrow = (const float4*)(h + (b * Gn + nb) * Dn) + half * 16;

    float u[8], v[8];
    #pragma unroll
    for (int l = 0; l < 8; l++) { u[l] = 0.f; v[l] = 0.f; }

    #pragma unroll 4
    for (int d4 = 0; d4 < 16; d4++) {
        float4 xv = __ldg(hrow + d4);
        float4 yv = __ldg(nrow + d4);
        float xs[4] = {xv.x, xv.y, xv.z, xv.w};
        float ys[4] = {yv.x, yv.y, yv.z, yv.w};
        #pragma unroll
        for (int r = 0; r < 4; r++) {
            int d = half * 64 + d4 * 4 + r;
            #pragma unroll
            for (int hh = 0; hh < Hn; hh++) {
                u[hh]     = fmaf(xs[r], sM[0][hh][d], u[hh]);
                u[4 + hh] = fmaf(ys[r], sM[1][hh][d], u[4 + hh]);
                v[hh]     = fmaf(xs[r], sM[2][hh][d], v[hh]);
                v[4 + hh] = fmaf(ys[r], sM[3][hh][d], v[4 + hh]);
            }
        }
    }
    if (half == 1) {
        #pragma unroll
        for (int l = 0; l < 8; l++) sX[gl][l] = u[l];
    } else {
        #pragma unroll
        for (int l = 0; l < 8; l++) sY[gl][l] = v[l];
    }
    __syncthreads();

    float z[8];
    if (half == 0) {
        #pragma unroll
        for (int l = 0; l < 8; l++) z[l] = u[l] + sX[gl][l];   // full u
    } else {
        #pragma unroll
        for (int l = 0; l < 8; l++) z[l] = sY[gl][l] + v[l];   // full v
    }

    float res[32];
    const float* Wslice = half ? &sW1[8][0] : &sW1[0][0];
    #pragma unroll
    for (int k = 0; k < 32; k++) {
        float a = half ? sB1[k] : 0.f;
        #pragma unroll
        for (int l = 0; l < 8; l++)
            a = fmaf(z[l], Wslice[l * 32 + k], a);
        res[k] = a;
    }

    uint32_t pk[16];
    #pragma unroll
    for (int m = 0; m < 16; m++) {
        int c = m >> 3, rem = m & 7, qq = rem >> 1, s = rem & 1;
        int k0 = 16 * c + 2 * qq + 8 * s;
        __half2 hp = __floats2half2_rn(res[k0], res[k0 + 1]);
        pk[m] = *(uint32_t*)&hp;
    }
    uint4* dst = half ? (uint4*)&g_Bvh2[(b * Gn + g) * 16]
                      : (uint4*)&g_Ah2 [(b * Gn + g) * 16];
    #pragma unroll
    for (int c4 = 0; c4 < 4; c4++)
        dst[c4] = make_uint4(pk[4*c4], pk[4*c4+1], pk[4*c4+2], pk[4*c4+3]);
}

// -------------------------------------------------------------------------
// mlp_mma (exact R14 config — measured best): fc2 via mma m16n8k16 fp16
// (f32 acc, bias pre-init), fc3 via MMA pair. Two i's per warp share
// pipelined Bv loads. 2 CTAs/SM — the pipeline needs the registers.
// -------------------------------------------------------------------------
#define BV_STRIDE 24   // uint32 per smem row (96B)

__global__ void __launch_bounds__(256, 2) mlp_mma(const float* __restrict__ W2,
                                                  const float* __restrict__ B2,
                                                  const float* __restrict__ W3,
                                                  const float* __restrict__ B3,
                                                  float* __restrict__ out) {
    extern __shared__ uint32_t sBv2[];   // [512][BV_STRIDE]
    const int t = threadIdx.x;
    const int w = t >> 5;
    const int lane = t & 31;
    const int q = lane & 3;          // threadID_in_group
    const int r = lane >> 2;         // groupID
    const int b = blockIdx.y;
    const int i0 = blockIdx.x * 16 + w * 2;   // this warp's two i's

    // ---- stage Bvh[b] into smem ----
    {
        const uint4* src = (const uint4*)&g_Bvh2[b * Gn * 16];
        for (int idx = t; idx < Gn * 4; idx += 256) {
            int j = idx >> 2, c4 = idx & 3;
            uint4 v = __ldg(src + idx);
            *(uint4*)&sBv2[j * BV_STRIDE + c4 * 4] = v;
        }
    }

    // ---- loop-invariant per-thread data ----
    uint2 Ah[2][2];   // [i][chunk]
    #pragma unroll
    for (int p = 0; p < 2; p++) {
        const uint32_t* ar = &g_Ah2[(b * Gn + i0 + p) * 16];
        Ah[p][0] = *(const uint2*)&ar[2 * q];
        Ah[p][1] = *(const uint2*)&ar[8 + 2 * q];
    }
    uint32_t wb[4][2][2];
    #pragma unroll
    for (int nbk = 0; nbk < 4; nbk++)
        #pragma unroll
        for (int c = 0; c < 2; c++) {
            int n = 8 * nbk + r;
            __half2 w0 = __floats2half2_rn(__ldg(&W2[(16*c + 2*q)     * 32 + n]),
                                           __ldg(&W2[(16*c + 2*q + 1) * 32 + n]));
            __half2 w1 = __floats2half2_rn(__ldg(&W2[(16*c + 2*q + 8) * 32 + n]),
                                           __ldg(&W2[(16*c + 2*q + 9) * 32 + n]));
            wb[nbk][c][0] = *(uint32_t*)&w0;
            wb[nbk][c][1] = *(uint32_t*)&w1;
        }
    uint32_t wb3[2][2];
    #pragma unroll
    for (int c = 0; c < 2; c++) {
        __half2 w0 = __floats2half2_rn(__ldg(&W3[16*c + 2*q]),
                                       __ldg(&W3[16*c + 2*q + 1]));
        __half2 w1 = __floats2half2_rn(__ldg(&W3[16*c + 2*q + 8]),
                                       __ldg(&W3[16*c + 2*q + 9]));
        wb3[c][0] = *(uint32_t*)&w0;
        wb3[c][1] = *(uint32_t*)&w1;
    }
    float b2v[4][2];
    #pragma unroll
    for (int nbk = 0; nbk < 4; nbk++) {
        b2v[nbk][0] = __ldg(&B2[8 * nbk + 2 * q]);
        b2v[nbk][1] = __ldg(&B2[8 * nbk + 2 * q + 1]);
    }
    const float b3 = __ldg(&B3[0]);
    const __half2 hz = __float2half2_rn(0.f);
    __syncthreads();

    float* outrow0 = out + ((size_t)(b * Gn + i0))     * Gn;
    float* outrow1 = out + ((size_t)(b * Gn + i0 + 1)) * Gn;
    const uint32_t* bvlo = sBv2 + r * BV_STRIDE + 2 * q;
    const uint32_t* bvhi = sBv2 + (r + 8) * BV_STRIDE + 2 * q;

    // prologue: load fragments for jt = 0
    uint2 rl[2], rh[2];
    rl[0] = *(const uint2*)(bvlo + 0); rl[1] = *(const uint2*)(bvlo + 8);
    rh[0] = *(const uint2*)(bvhi + 0); rh[1] = *(const uint2*)(bvhi + 8);

    for (int jt = 0; jt < 32; jt++) {
        const int j0 = jt * 16;
        // prefetch next tile's fragments (clamped; unused on last iter)
        const int jn = (jt < 31) ? (j0 + 16) : 0;
        const uint32_t* npl = bvlo + jn * BV_STRIDE;
        const uint32_t* nph = bvhi + jn * BV_STRIDE;
        uint2 nl0 = *(const uint2*)(npl + 0);
        uint2 nl1 = *(const uint2*)(npl + 8);
        uint2 nh0 = *(const uint2*)(nph + 0);
        uint2 nh1 = *(const uint2*)(nph + 8);

        float acc[2][4][4];
        #pragma unroll
        for (int p = 0; p < 2; p++)
            #pragma unroll
            for (int nbk = 0; nbk < 4; nbk++) {
                acc[p][nbk][0] = b2v[nbk][0]; acc[p][nbk][1] = b2v[nbk][1];
                acc[p][nbk][2] = b2v[nbk][0]; acc[p][nbk][3] = b2v[nbk][1];
            }

        #pragma unroll
        for (int c = 0; c < 2; c++) {
            uint32_t a[2][4];
            #pragma unroll
            for (int p = 0; p < 2; p++) {
                __half2 av0 = *(__half2*)&Ah[p][c].x;
                __half2 av1 = *(__half2*)&Ah[p][c].y;
                __half2 f0 = __hmax2(__hadd2(av0, *(__half2*)&rl[c].x), hz);
                __half2 f1 = __hmax2(__hadd2(av0, *(__half2*)&rh[c].x), hz);
                __half2 f2 = __hmax2(__hadd2(av1, *(__half2*)&rl[c].y), hz);
                __half2 f3 = __hmax2(__hadd2(av1, *(__half2*)&rh[c].y), hz);
                a[p][0] = *(uint32_t*)&f0; a[p][1] = *(uint32_t*)&f1;
                a[p][2] = *(uint32_t*)&f2; a[p][3] = *(uint32_t*)&f3;
            }
            #pragma unroll
            for (int nbk = 0; nbk < 4; nbk++)
                #pragma unroll
                for (int p = 0; p < 2; p++) {
                    asm volatile(
                        "mma.sync.aligned.m16n8k16.row.col.f32.f16.f16.f32 "
                        "{%0,%1,%2,%3}, {%4,%5,%6,%7}, {%8,%9}, {%0,%1,%2,%3};"
                        : "+f"(acc[p][nbk][0]), "+f"(acc[p][nbk][1]),
                          "+f"(acc[p][nbk][2]), "+f"(acc[p][nbk][3])
                        : "r"(a[p][0]), "r"(a[p][1]), "r"(a[p][2]), "r"(a[p][3]),
                          "r"(wb[nbk][c][0]), "r"(wb[nbk][c][1]));
                }
        }

        // rotate prefetched fragments in
        rl[0] = nl0; rl[1] = nl1; rh[0] = nh0; rh[1] = nh1;

        // ---- epilogue: relu-pack acc as A-fragments, fc3 via 2 HMMA/i ----
        float o[2][2];
        #pragma unroll
        for (int p = 0; p < 2; p++) {
            float o0 = b3, o1 = 0.f, o2 = b3, o3 = 0.f;
            #pragma unroll
            for (int c = 0; c < 2; c++) {
                __half2 g0 = __hmax2(__floats2half2_rn(acc[p][2*c][0],   acc[p][2*c][1]),   hz);
                __half2 g1 = __hmax2(__floats2half2_rn(acc[p][2*c][2],   acc[p][2*c][3]),   hz);
                __half2 g2 = __hmax2(__floats2half2_rn(acc[p][2*c+1][0], acc[p][2*c+1][1]), hz);
                __half2 g3 = __hmax2(__floats2half2_rn(acc[p][2*c+1][2], acc[p][2*c+1][3]), hz);
                uint32_t a0 = *(uint32_t*)&g0, a1 = *(uint32_t*)&g1;
                uint32_t a2 = *(uint32_t*)&g2, a3 = *(uint32_t*)&g3;
                asm volatile(
                    "mma.sync.aligned.m16n8k16.row.col.f32.f16.f16.f32 "
                    "{%0,%1,%2,%3}, {%4,%5,%6,%7}, {%8,%9}, {%0,%1,%2,%3};"
                    : "+f"(o0), "+f"(o1), "+f"(o2), "+f"(o3)
                    : "r"(a0), "r"(a1), "r"(a2), "r"(a3),
                      "r"(wb3[c][0]), "r"(wb3[c][1]));
            }
            o[p][0] = o0; o[p][1] = o2;
        }
        if (q == 0) {
            outrow0[j0 + r]     = o[0][0];
            outrow0[j0 + 8 + r] = o[0][1];
            outrow1[j0 + r]     = o[1][0];
            outrow1[j0 + 8 + r] = o[1][1];
        }
    }
}

// -------------------------------------------------------------------------
extern "C" void kernel_launch(void* const* d_in, const int* in_sizes, int n_in,
                              void* d_out, int out_size) {
    const float* h    = (const float*)d_in[0];
    const int*   pp   = (const int*)  d_in[1];
    const int*   pd   = (const int*)  d_in[2];
    const int*   rec  = (const int*)  d_in[3];
    const float* Wq1  = (const float*)d_in[4];
    const float* Wk1  = (const float*)d_in[5];
    const float* Wq2  = (const float*)d_in[6];
    const float* Wk2  = (const float*)d_in[7];
    const float* FC1W = (const float*)d_in[8];
    const float* FC1B = (const float*)d_in[9];
    const float* W2   = (const float*)d_in[10];
    const float* B2   = (const float*)d_in[11];
    const float* W3   = (const float*)d_in[12];
    const float* B3   = (const float*)d_in[13];

    const int smem_bytes = Gn * BV_STRIDE * sizeof(uint32_t);   // 49152
    static int smem_set = 0;
    if (!smem_set) {
        cudaFuncSetAttribute(mlp_mma, cudaFuncAttributeMaxDynamicSharedMemorySize, smem_bytes);
        smem_set = 1;
    }

    prep<<<dim3(4, Bn), 256>>>(h, pp, pd, rec, Wq1, Wk1, Wq2, Wk2, FC1W, FC1B);
    mlp_mma<<<dim3(Gn / 16, Bn), 256, smem_bytes>>>(W2, B2, W3, B3, (float*)d_out);
}